// round 5
// baseline (speedup 1.0000x reference)
#include <cuda_runtime.h>

// ---------------------------------------------------------------------------
// MultiLoss_JSD: fused MSE + 17-head CE + histogram JSD
// B = 262144 rows; decoded/true: [B,168] f32; encoded: [B,11] f32; label: [B,1] f32
// out: 4 floats [multi, mse, ce, 0.1*kld]
// ---------------------------------------------------------------------------

#define NSLICE 17
#define NBINS  800
#define NCOLS  168
#define RATIO_JSD 0.1
#define FIN_BLOCKS 16

// Compile-time column -> CE-slice classification.
// Slice boundary at col 84 splits slices cleanly: 0..6 below, 7..16 at/above.
__host__ __device__ constexpr int slice_of(int c) {
    const int S[NSLICE][2] = {
        {1,10},{12,29},{30,33},{33,40},{40,64},{64,79},{79,84},{84,94},{94,96},
        {96,99},{99,105},{105,113},{116,122},{122,128},{128,151},{151,159},{160,165}};
    for (int i = 0; i < NSLICE; i++)
        if (c >= S[i][0] && c < S[i][1]) return i;
    return -1;  // MSE column
}

// ---------------- scratch (device globals; zero at module load) ------------
__device__ double   g_mse;
__device__ double   g_ce;
__device__ double   g_kld;
__device__ unsigned g_done;
__device__ unsigned g_min[10];
__device__ unsigned g_max[10];
__device__ int      g_male;
__device__ int      g_hist[2][10][NBINS];   // [sex][dim][bin]

// ordered-uint encoding of float for atomicMin/Max
__device__ __forceinline__ unsigned f2o(float f) {
    unsigned u = __float_as_uint(f);
    return (u & 0x80000000u) ? ~u : (u | 0x80000000u);
}
__device__ __forceinline__ float o2f(unsigned u) {
    return (u & 0x80000000u) ? __uint_as_float(u & 0x7FFFFFFFu)
                             : __uint_as_float(~u);
}

// NOTE: scratch identities are maintained by finalize_kernel (it re-zeros
// everything it consumed), so no init kernel is needed per replay.
// g_min identity = 0xFFFFFFFF (max uint), g_max identity = 0.

// ---------------- compile-time unrolled column handling --------------------
template <int C>
__device__ __forceinline__ void handle_col(float d, float t,
                                           float (&se)[NSLICE],
                                           float& dlab, float& msea) {
    constexpr int s = slice_of(C);
    if constexpr (s >= 0) {
        se[s] += __expf(d);
        dlab = __fmaf_rn(d, t, dlab);   // t is exact one-hot 0/1
    } else {
        float diff = d - t;
        msea = __fmaf_rn(diff, diff, msea);
    }
}

template <int I, int HI>
__device__ __forceinline__ void cols_loop(const float4* __restrict__ dp,
                                          const float4* __restrict__ tp,
                                          float (&se)[NSLICE],
                                          float& dlab, float& msea) {
    if constexpr (I < HI) {
        float4 d = __ldg(dp + I);
        float4 t = __ldg(tp + I);
        handle_col<4 * I + 0>(d.x, t.x, se, dlab, msea);
        handle_col<4 * I + 1>(d.y, t.y, se, dlab, msea);
        handle_col<4 * I + 2>(d.z, t.z, se, dlab, msea);
        handle_col<4 * I + 3>(d.w, t.w, se, dlab, msea);
        cols_loop<I + 1, HI>(dp, tp, se, dlab, msea);
    }
}

template <int S0, int S1>
__device__ __forceinline__ float ce_logs(const float (&se)[NSLICE]) {
    float c = 0.0f;
#pragma unroll
    for (int s = S0; s < S1; s++) c += __logf(se[s]);
    return c;
}

// ---------------- main pass: MSE + CE + minmax + male count ----------------
// Each row is processed by TWO warps: even warp -> cols [0,84), odd warp ->
// cols [84,168). Split is warp-uniform (no divergence) and slice-clean, so
// partial CE/MSE sums just add into the block reduction.
__global__ void __launch_bounds__(256) main_kernel(
    const float* __restrict__ enc, const float* __restrict__ dec,
    const float* __restrict__ tru, const float* __restrict__ lab, int B) {

    __shared__ float    s_ce[8], s_mse[8];
    __shared__ unsigned s_mn[10], s_mx[10];
    __shared__ int      s_male;

    int tid  = threadIdx.x;
    int wid  = tid >> 5;
    int lane = tid & 31;
    if (tid < 10) { s_mn[tid] = 0xFFFFFFFFu; s_mx[tid] = 0u; }
    if (tid == 0) s_male = 0;
    __syncthreads();

    // 4 row-groups of 32 rows per block (256 threads, 2 warps per group)
    int group = blockIdx.x * 4 + (wid >> 1);
    int row   = group * 32 + lane;
    int half  = wid & 1;           // warp-uniform

    float ce_row = 0.0f, msea = 0.0f;

    if (row < B) {
        float se[NSLICE];
#pragma unroll
        for (int i = 0; i < NSLICE; i++) se[i] = 0.0f;
        float dlab = 0.0f;

        const float4* dp = (const float4*)(dec + (size_t)row * NCOLS);
        const float4* tp = (const float4*)(tru + (size_t)row * NCOLS);

        if (half == 0) {
            cols_loop<0, 21>(dp, tp, se, dlab, msea);   // cols 0..83
            ce_row = ce_logs<0, 7>(se) - dlab;          // slices 0..6
        } else {
            cols_loop<21, 42>(dp, tp, se, dlab, msea);  // cols 84..167
            ce_row = ce_logs<7, 17>(se) - dlab;         // slices 7..16
        }
    }

    // ce/mse warp reductions (all warps)
    float cer = ce_row, mser = msea;
#pragma unroll
    for (int o = 16; o; o >>= 1) {
        cer  += __shfl_xor_sync(0xFFFFFFFFu, cer,  o);
        mser += __shfl_xor_sync(0xFFFFFFFFu, mser, o);
    }
    if (lane == 0) { s_ce[wid] = cer; s_mse[wid] = mser; }

    // enc min/max + male count: even warps only (one pass per row)
    if (half == 0) {
        float emn[10], emx[10];
        bool is_male = false;
        if (row < B) {
            const float* ep = enc + (size_t)row * 11;
#pragma unroll
            for (int j = 0; j < 10; j++) {
                float v = __ldg(ep + j);
                emn[j] = v; emx[j] = v;
            }
            is_male = (__ldg(lab + row) < 0.5f);
        } else {
#pragma unroll
            for (int j = 0; j < 10; j++) {
                emn[j] = __int_as_float(0x7F800000);   // +inf
                emx[j] = __int_as_float(0xFF800000);   // -inf
            }
        }
#pragma unroll
        for (int j = 0; j < 10; j++) {
            float mn = emn[j], mx = emx[j];
#pragma unroll
            for (int o = 16; o; o >>= 1) {
                mn = fminf(mn, __shfl_xor_sync(0xFFFFFFFFu, mn, o));
                mx = fmaxf(mx, __shfl_xor_sync(0xFFFFFFFFu, mx, o));
            }
            emn[j] = mn; emx[j] = mx;
        }
        unsigned mb = __ballot_sync(0xFFFFFFFFu, is_male);
        if (lane == 0) {
#pragma unroll
            for (int j = 0; j < 10; j++) {
                atomicMin(&s_mn[j], f2o(emn[j]));
                atomicMax(&s_mx[j], f2o(emx[j]));
            }
            atomicAdd(&s_male, __popc(mb));
        }
    }
    __syncthreads();

    if (tid == 0) {
        float c = 0.0f, m = 0.0f;
#pragma unroll
        for (int w = 0; w < 8; w++) { c += s_ce[w]; m += s_mse[w]; }
        atomicAdd(&g_ce,  (double)c);
        atomicAdd(&g_mse, (double)m);
        atomicAdd(&g_male, s_male);
    }
    if (tid < 10) {
        atomicMin(&g_min[tid], s_mn[tid]);
        atomicMax(&g_max[tid], s_mx[tid]);
    }
}

// ---------------- histogram pass (one sex per blockIdx.y) ------------------
__global__ void __launch_bounds__(256) hist_kernel(
    const float* __restrict__ enc, const float* __restrict__ lab, int B) {

    __shared__ int sh[10 * NBINS];   // 32 KB
    for (int i = threadIdx.x; i < 10 * NBINS; i += 256) sh[i] = 0;
    __syncthreads();

    int sex = blockIdx.y;   // 0 = male (label 0), 1 = female (label 1)

    float mnv[10], rng[10];
#pragma unroll
    for (int j = 0; j < 10; j++) {
        mnv[j] = o2f(g_min[j]);
        rng[j] = o2f(g_max[j]) - mnv[j];
    }

    int stride = gridDim.x * blockDim.x;
    for (int row = blockIdx.x * blockDim.x + threadIdx.x; row < B; row += stride) {
        float lv = __ldg(lab + row);
        int rsex = (lv < 0.5f) ? 0 : 1;
        if (rsex != sex) continue;
        const float* ep = enc + (size_t)row * 11;
#pragma unroll
        for (int j = 0; j < 10; j++) {
            float x = __ldg(ep + j);
            // match jax fp32: t = (x-mn)/(mx-mn); idx = clip(floor(t*800),0,799)
            float t  = __fdiv_rn(x - mnv[j], rng[j]);
            float ft = floorf(__fmul_rn(t, (float)NBINS));
            int idx = (int)ft;
            idx = max(0, min(NBINS - 1, idx));
            atomicAdd(&sh[j * NBINS + idx], 1);
        }
    }
    __syncthreads();

    int* gh = &g_hist[sex][0][0];
    for (int i = threadIdx.x; i < 10 * NBINS; i += 256) {
        int v = sh[i];
        if (v) atomicAdd(&gh[i], v);
    }
}

// ---------------- finalize: multi-block JSD + combine + scratch reset ------
__global__ void __launch_bounds__(256) finalize_kernel(float* __restrict__ out, int B) {
    __shared__ double sred[8];

    int nmale = g_male;                 // read before any reset
    float nm_inv = 1.0f / (float)nmale;
    float nf_inv = 1.0f / (float)(B - nmale);
    const float eps = 1e-12f;

    float acc = 0.0f;
    int* hm = &g_hist[0][0][0];
    int* hf = &g_hist[1][0][0];
    for (int i = blockIdx.x * 256 + threadIdx.x; i < 10 * NBINS;
         i += FIN_BLOCKS * 256) {
        int a = hm[i], b = hf[i];
        hm[i] = 0; hf[i] = 0;           // re-zero for next replay
        float m = (float)a * nm_inv;
        float f = (float)b * nf_inv;
        float mid = 0.5f * (m + f);
        float inv_mid = 1.0f / (mid + eps);
        if (m > 0.0f) acc += m * logf((m + eps) * inv_mid);
        if (f > 0.0f) acc += f * logf((f + eps) * inv_mid);
    }

    double d = (double)acc;
#pragma unroll
    for (int o = 16; o; o >>= 1)
        d += __shfl_xor_sync(0xFFFFFFFFu, d, o);
    int wid = threadIdx.x >> 5;
    if ((threadIdx.x & 31) == 0) sred[wid] = d;
    __syncthreads();

    if (threadIdx.x == 0) {
        double s = 0.0;
#pragma unroll
        for (int w = 0; w < 8; w++) s += sred[w];
        atomicAdd(&g_kld, s);
        __threadfence();
        unsigned ticket = atomicAdd(&g_done, 1u);
        if (ticket == FIN_BLOCKS - 1) {
            // all blocks have accumulated (their fence precedes their ticket)
            double kld = 0.5 * atomicAdd(&g_kld, 0.0);
            double mse = g_mse / (double)B;
            double ce  = g_ce  / (double)B;
            out[0] = (float)((1.0 - RATIO_JSD) * (mse + ce) + RATIO_JSD * kld);
            out[1] = (float)mse;
            out[2] = (float)ce;
            out[3] = (float)(RATIO_JSD * kld);
            // reset scalar scratch for the next replay
            g_mse = 0.0; g_ce = 0.0; g_kld = 0.0;
            g_male = 0; g_done = 0u;
#pragma unroll
            for (int j = 0; j < 10; j++) {
                g_min[j] = 0xFFFFFFFFu;
                g_max[j] = 0u;
            }
        }
    }
}

// ---------------- launch ----------------------------------------------------
extern "C" void kernel_launch(void* const* d_in, const int* in_sizes, int n_in,
                              void* d_out, int out_size) {
    const float* enc = (const float*)d_in[0];   // [B,11]
    const float* dec = (const float*)d_in[1];   // [B,168]
    const float* tru = (const float*)d_in[2];   // [B,168]
    const float* lab = (const float*)d_in[3];   // [B,1]
    int B = in_sizes[3];

    int blocks = (B + 127) / 128;               // 128 rows per block (2 warps/row-group)
    main_kernel<<<blocks, 256>>>(enc, dec, tru, lab, B);

    dim3 hgrid(128, 2, 1);
    hist_kernel<<<hgrid, 256>>>(enc, lab, B);

    finalize_kernel<<<FIN_BLOCKS, 256>>>((float*)d_out, B);
}

// round 6
// speedup vs baseline: 1.0649x; 1.0649x over previous
#include <cuda_runtime.h>

// ---------------------------------------------------------------------------
// MultiLoss_JSD: fused MSE + 17-head CE + histogram JSD
// B = 262144 rows; decoded/true: [B,168] f32; encoded: [B,11] f32; label: [B,1] f32
// out: 4 floats [multi, mse, ce, 0.1*kld]
// ---------------------------------------------------------------------------

#define NSLICE 17
#define NBINS  800
#define NCOLS  168
#define NF4    42          // float4s per row
#define RATIO_JSD 0.1
#define FIN_BLOCKS 16
#define ROWS_PB 256        // rows per block == threads per block
#define NCHUNK  9          // 8 chunks of 5 float4 + 1 chunk of 2 float4

__host__ __device__ constexpr int chunk_nf(int ch) { return (ch == 8) ? 2 : 5; }
__host__ __device__ constexpr int chunk_f4base(int ch) { return ch * 5; }

// Compile-time column -> CE-slice classification.
__host__ __device__ constexpr int slice_of(int c) {
    const int S[NSLICE][2] = {
        {1,10},{12,29},{30,33},{33,40},{40,64},{64,79},{79,84},{84,94},{94,96},
        {96,99},{99,105},{105,113},{116,122},{122,128},{128,151},{151,159},{160,165}};
    for (int i = 0; i < NSLICE; i++)
        if (c >= S[i][0] && c < S[i][1]) return i;
    return -1;  // MSE column
}

// ---------------- scratch (device globals; zero at module load) ------------
// finalize_kernel re-zeros everything it consumed, so no init kernel needed.
__device__ double   g_mse;
__device__ double   g_ce;
__device__ double   g_kld;
__device__ unsigned g_done;
__device__ unsigned g_min[10];
__device__ unsigned g_max[10];
__device__ int      g_male;
__device__ int      g_hist[2][10][NBINS];   // [sex][dim][bin]

__device__ __forceinline__ unsigned f2o(float f) {
    unsigned u = __float_as_uint(f);
    return (u & 0x80000000u) ? ~u : (u | 0x80000000u);
}
__device__ __forceinline__ float o2f(unsigned u) {
    return (u & 0x80000000u) ? __uint_as_float(u & 0x7FFFFFFFu)
                             : __uint_as_float(~u);
}

// ---------------- compile-time column handling -----------------------------
template <int C>
__device__ __forceinline__ void handle_col(float d, float t,
                                           float (&se)[NSLICE],
                                           float& dlab, float& msea) {
    constexpr int s = slice_of(C);
    if constexpr (s >= 0) {
        se[s] += __expf(d);
        dlab = __fmaf_rn(d, t, dlab);   // t is exact one-hot 0/1
    } else {
        float diff = d - t;
        msea = __fmaf_rn(diff, diff, msea);
    }
}

// ---------------- chunked smem-staged row processing -----------------------
// Coalesced load of chunk CH into registers (per-thread NF float4 per array).
template <int CH>
__device__ __forceinline__ void load_chunk(const float4* __restrict__ dp,
                                           const float4* __restrict__ tp,
                                           int tid, int maxrow,
                                           float4 (&ra)[5], float4 (&rb)[5]) {
    constexpr int NF = chunk_nf(CH);
#pragma unroll
    for (int i = 0; i < NF; i++) {
        int p   = i * ROWS_PB + tid;
        int row = p / NF;                 // constant divisor -> mul/shift
        int col = p - row * NF;
        row = min(row, maxrow);
        size_t g = (size_t)row * NF4 + chunk_f4base(CH) + col;
        ra[i] = __ldg(dp + g);
        rb[i] = __ldg(tp + g);
    }
}

template <int CH>
__device__ __forceinline__ void store_chunk(float4* s_a, float4* s_b, int tid,
                                            const float4 (&ra)[5],
                                            const float4 (&rb)[5]) {
    constexpr int NF = chunk_nf(CH);
#pragma unroll
    for (int i = 0; i < NF; i++) {
        int p = i * ROWS_PB + tid;        // lane-contiguous STS, conflict-free
        s_a[p] = ra[i];
        s_b[p] = rb[i];
    }
}

template <int CH, int J>
__device__ __forceinline__ void compute_rec(const float4* s_a, const float4* s_b,
                                            int tid, float (&se)[NSLICE],
                                            float& dlab, float& msea) {
    constexpr int NF = chunk_nf(CH);
    if constexpr (J < NF) {
        float4 a = s_a[tid * NF + J];     // stride NF*16B: conflict-free LDS.128
        float4 b = s_b[tid * NF + J];
        constexpr int C = (chunk_f4base(CH) + J) * 4;
        handle_col<C + 0>(a.x, b.x, se, dlab, msea);
        handle_col<C + 1>(a.y, b.y, se, dlab, msea);
        handle_col<C + 2>(a.z, b.z, se, dlab, msea);
        handle_col<C + 3>(a.w, b.w, se, dlab, msea);
        compute_rec<CH, J + 1>(s_a, s_b, tid, se, dlab, msea);
    }
}

template <int CH>
__device__ __forceinline__ void chunks_loop(const float4* __restrict__ dp,
                                            const float4* __restrict__ tp,
                                            float4* s_a, float4* s_b,
                                            int tid, int maxrow,
                                            float4 (&ra)[5], float4 (&rb)[5],
                                            float (&se)[NSLICE],
                                            float& dlab, float& msea) {
    if constexpr (CH < NCHUNK) {
        __syncthreads();                       // smem free (prev compute done)
        store_chunk<CH>(s_a, s_b, tid, ra, rb);
        __syncthreads();
        if constexpr (CH + 1 < NCHUNK)
            load_chunk<CH + 1>(dp, tp, tid, maxrow, ra, rb);  // overlap w/ compute
        compute_rec<CH, 0>(s_a, s_b, tid, se, dlab, msea);
        chunks_loop<CH + 1>(dp, tp, s_a, s_b, tid, maxrow, ra, rb, se, dlab, msea);
    }
}

// ---------------- main pass: MSE + CE + minmax + male count ----------------
__global__ void __launch_bounds__(ROWS_PB) main_kernel(
    const float* __restrict__ enc, const float* __restrict__ dec,
    const float* __restrict__ tru, const float* __restrict__ lab, int B) {

    __shared__ float4   s_a[ROWS_PB * 5];    // 20 KB
    __shared__ float4   s_b[ROWS_PB * 5];    // 20 KB
    __shared__ float    s_ce[8], s_mse[8];
    __shared__ unsigned s_mn[10], s_mx[10];
    __shared__ int      s_male;

    int tid  = threadIdx.x;
    int wid  = tid >> 5;
    int lane = tid & 31;
    if (tid < 10) { s_mn[tid] = 0xFFFFFFFFu; s_mx[tid] = 0u; }
    if (tid == 0) s_male = 0;

    int base   = blockIdx.x * ROWS_PB;
    int maxrow = min(ROWS_PB, B - base) - 1;   // clamp for safe loads
    int row    = base + tid;
    bool valid = (row < B);

    const float4* dp = (const float4*)(dec + (size_t)base * NCOLS);
    const float4* tp = (const float4*)(tru + (size_t)base * NCOLS);

    float se[NSLICE];
#pragma unroll
    for (int i = 0; i < NSLICE; i++) se[i] = 0.0f;
    float dlab = 0.0f, msea = 0.0f;

    float4 ra[5], rb[5];
    load_chunk<0>(dp, tp, tid, maxrow, ra, rb);
    chunks_loop<0>(dp, tp, s_a, s_b, tid, maxrow, ra, rb, se, dlab, msea);

    float ce_row = 0.0f;
#pragma unroll
    for (int i = 0; i < NSLICE; i++) ce_row += __logf(se[i]);
    ce_row -= dlab;
    if (!valid) { ce_row = 0.0f; msea = 0.0f; }

    // enc min/max + male flag (thread-per-row)
    float emn[10], emx[10];
    bool is_male = false;
    if (valid) {
        const float* ep = enc + (size_t)row * 11;
#pragma unroll
        for (int j = 0; j < 10; j++) {
            float v = __ldg(ep + j);
            emn[j] = v; emx[j] = v;
        }
        is_male = (__ldg(lab + row) < 0.5f);
    } else {
#pragma unroll
        for (int j = 0; j < 10; j++) {
            emn[j] = __int_as_float(0x7F800000);   // +inf
            emx[j] = __int_as_float(0xFF800000);   // -inf
        }
    }

    // warp reductions
    float cer = ce_row, mser = msea;
#pragma unroll
    for (int o = 16; o; o >>= 1) {
        cer  += __shfl_xor_sync(0xFFFFFFFFu, cer,  o);
        mser += __shfl_xor_sync(0xFFFFFFFFu, mser, o);
    }
#pragma unroll
    for (int j = 0; j < 10; j++) {
        float mn = emn[j], mx = emx[j];
#pragma unroll
        for (int o = 16; o; o >>= 1) {
            mn = fminf(mn, __shfl_xor_sync(0xFFFFFFFFu, mn, o));
            mx = fmaxf(mx, __shfl_xor_sync(0xFFFFFFFFu, mx, o));
        }
        emn[j] = mn; emx[j] = mx;
    }
    unsigned mb = __ballot_sync(0xFFFFFFFFu, is_male);

    if (lane == 0) {
        s_ce[wid]  = cer;
        s_mse[wid] = mser;
#pragma unroll
        for (int j = 0; j < 10; j++) {
            atomicMin(&s_mn[j], f2o(emn[j]));
            atomicMax(&s_mx[j], f2o(emx[j]));
        }
        atomicAdd(&s_male, __popc(mb));
    }
    __syncthreads();

    if (tid == 0) {
        float c = 0.0f, m = 0.0f;
#pragma unroll
        for (int w = 0; w < 8; w++) { c += s_ce[w]; m += s_mse[w]; }
        atomicAdd(&g_ce,  (double)c);
        atomicAdd(&g_mse, (double)m);
        atomicAdd(&g_male, s_male);
    }
    if (tid < 10) {
        atomicMin(&g_min[tid], s_mn[tid]);
        atomicMax(&g_max[tid], s_mx[tid]);
    }
}

// ---------------- histogram pass (one sex per blockIdx.y) ------------------
__global__ void __launch_bounds__(256) hist_kernel(
    const float* __restrict__ enc, const float* __restrict__ lab, int B) {

    __shared__ int sh[10 * NBINS];   // 32 KB
    for (int i = threadIdx.x; i < 10 * NBINS; i += 256) sh[i] = 0;
    __syncthreads();

    int sex = blockIdx.y;   // 0 = male (label 0), 1 = female (label 1)

    float mnv[10], rng[10];
#pragma unroll
    for (int j = 0; j < 10; j++) {
        mnv[j] = o2f(g_min[j]);
        rng[j] = o2f(g_max[j]) - mnv[j];
    }

    int stride = gridDim.x * blockDim.x;
    for (int row = blockIdx.x * blockDim.x + threadIdx.x; row < B; row += stride) {
        float lv = __ldg(lab + row);
        int rsex = (lv < 0.5f) ? 0 : 1;
        if (rsex != sex) continue;
        const float* ep = enc + (size_t)row * 11;
#pragma unroll
        for (int j = 0; j < 10; j++) {
            float x = __ldg(ep + j);
            // match jax fp32: t = (x-mn)/(mx-mn); idx = clip(floor(t*800),0,799)
            float t  = __fdiv_rn(x - mnv[j], rng[j]);
            float ft = floorf(__fmul_rn(t, (float)NBINS));
            int idx = (int)ft;
            idx = max(0, min(NBINS - 1, idx));
            atomicAdd(&sh[j * NBINS + idx], 1);
        }
    }
    __syncthreads();

    int* gh = &g_hist[sex][0][0];
    for (int i = threadIdx.x; i < 10 * NBINS; i += 256) {
        int v = sh[i];
        if (v) atomicAdd(&gh[i], v);
    }
}

// ---------------- finalize: multi-block JSD + combine + scratch reset ------
__global__ void __launch_bounds__(256) finalize_kernel(float* __restrict__ out, int B) {
    __shared__ double sred[8];

    int nmale = g_male;                 // read before any reset
    float nm_inv = 1.0f / (float)nmale;
    float nf_inv = 1.0f / (float)(B - nmale);
    const float eps = 1e-12f;

    float acc = 0.0f;
    int* hm = &g_hist[0][0][0];
    int* hf = &g_hist[1][0][0];
    for (int i = blockIdx.x * 256 + threadIdx.x; i < 10 * NBINS;
         i += FIN_BLOCKS * 256) {
        int a = hm[i], b = hf[i];
        hm[i] = 0; hf[i] = 0;           // re-zero for next replay
        float m = (float)a * nm_inv;
        float f = (float)b * nf_inv;
        float mid = 0.5f * (m + f);
        float inv_mid = 1.0f / (mid + eps);
        if (m > 0.0f) acc += m * logf((m + eps) * inv_mid);
        if (f > 0.0f) acc += f * logf((f + eps) * inv_mid);
    }

    double d = (double)acc;
#pragma unroll
    for (int o = 16; o; o >>= 1)
        d += __shfl_xor_sync(0xFFFFFFFFu, d, o);
    int wid = threadIdx.x >> 5;
    if ((threadIdx.x & 31) == 0) sred[wid] = d;
    __syncthreads();

    if (threadIdx.x == 0) {
        double s = 0.0;
#pragma unroll
        for (int w = 0; w < 8; w++) s += sred[w];
        atomicAdd(&g_kld, s);
        __threadfence();
        unsigned ticket = atomicAdd(&g_done, 1u);
        if (ticket == FIN_BLOCKS - 1) {
            double kld = 0.5 * atomicAdd(&g_kld, 0.0);
            double mse = g_mse / (double)B;
            double ce  = g_ce  / (double)B;
            out[0] = (float)((1.0 - RATIO_JSD) * (mse + ce) + RATIO_JSD * kld);
            out[1] = (float)mse;
            out[2] = (float)ce;
            out[3] = (float)(RATIO_JSD * kld);
            // reset scalar scratch for the next replay
            g_mse = 0.0; g_ce = 0.0; g_kld = 0.0;
            g_male = 0; g_done = 0u;
#pragma unroll
            for (int j = 0; j < 10; j++) {
                g_min[j] = 0xFFFFFFFFu;
                g_max[j] = 0u;
            }
        }
    }
}

// ---------------- launch ----------------------------------------------------
extern "C" void kernel_launch(void* const* d_in, const int* in_sizes, int n_in,
                              void* d_out, int out_size) {
    const float* enc = (const float*)d_in[0];   // [B,11]
    const float* dec = (const float*)d_in[1];   // [B,168]
    const float* tru = (const float*)d_in[2];   // [B,168]
    const float* lab = (const float*)d_in[3];   // [B,1]
    int B = in_sizes[3];

    int blocks = (B + ROWS_PB - 1) / ROWS_PB;
    main_kernel<<<blocks, ROWS_PB>>>(enc, dec, tru, lab, B);

    dim3 hgrid(128, 2, 1);
    hist_kernel<<<hgrid, 256>>>(enc, lab, B);

    finalize_kernel<<<FIN_BLOCKS, 256>>>((float*)d_out, B);
}

// round 7
// speedup vs baseline: 1.2827x; 1.2046x over previous
#include <cuda_runtime.h>
#include <cstdint>

// ---------------------------------------------------------------------------
// MultiLoss_JSD: fused MSE + 17-head CE + histogram JSD
// B = 262144 rows; decoded/true: [B,168] f32; encoded: [B,11] f32; label: [B,1] f32
// out: 4 floats [multi, mse, ce, 0.1*kld]
// ---------------------------------------------------------------------------

#define NSLICE 17
#define NBINS  800
#define NCOLS  168
#define NF4    42          // float4s per row
#define NF     2           // float4s per chunk per row
#define NCH    21          // 21 chunks * 8 cols = 168
#define ROWS_PB 256
#define RATIO_JSD 0.1
#define FIN_BLOCKS 16

__host__ __device__ constexpr int slice_of(int c) {
    const int S[NSLICE][2] = {
        {1,10},{12,29},{30,33},{33,40},{40,64},{64,79},{79,84},{84,94},{94,96},
        {96,99},{99,105},{105,113},{116,122},{122,128},{128,151},{151,159},{160,165}};
    for (int i = 0; i < NSLICE; i++)
        if (c >= S[i][0] && c < S[i][1]) return i;
    return -1;  // MSE column
}

// ---------------- scratch (device globals; zero at module load) ------------
// finalize_kernel re-zeros everything it consumed, so no init kernel needed.
__device__ double   g_mse;
__device__ double   g_ce;
__device__ double   g_kld;
__device__ unsigned g_done;
__device__ unsigned g_min[10];
__device__ unsigned g_max[10];
__device__ int      g_male;
__device__ int      g_hist[2][10][NBINS];   // [sex][dim][bin]

__device__ __forceinline__ unsigned f2o(float f) {
    unsigned u = __float_as_uint(f);
    return (u & 0x80000000u) ? ~u : (u | 0x80000000u);
}
__device__ __forceinline__ float o2f(unsigned u) {
    return (u & 0x80000000u) ? __uint_as_float(u & 0x7FFFFFFFu)
                             : __uint_as_float(~u);
}

// ---------------- cp.async helpers -----------------------------------------
__device__ __forceinline__ void cp_async16(uint32_t s, const void* g) {
    asm volatile("cp.async.cg.shared.global [%0], [%1], 16;" :: "r"(s), "l"(g));
}
__device__ __forceinline__ void cp_commit() {
    asm volatile("cp.async.commit_group;" ::: "memory");
}
template <int N>
__device__ __forceinline__ void cp_wait() {
    asm volatile("cp.async.wait_group %0;" :: "n"(N) : "memory");
}

// ---------------- compile-time column handling -----------------------------
template <int C>
__device__ __forceinline__ void handle_col(float d, float t,
                                           float (&se)[NSLICE],
                                           float& dlab, float& msea) {
    constexpr int s = slice_of(C);
    if constexpr (s >= 0) {
        se[s] += __expf(d);
        dlab = __fmaf_rn(d, t, dlab);   // t is exact one-hot 0/1
    } else {
        float diff = d - t;
        msea = __fmaf_rn(diff, diff, msea);
    }
}

// issue chunk CH into buffer (CH&1): 4 cp.async per thread, lane-contiguous
template <int CH>
__device__ __forceinline__ void issue_chunk(uint32_t sa0, uint32_t sa1,
                                            uint32_t sb0, uint32_t sb1, int tid,
                                            const float4* g0a, const float4* g1a,
                                            const float4* g0b, const float4* g1b) {
    constexpr uint32_t BUFB = (uint32_t)((CH & 1) ? 1 : 0);
    uint32_t sa = BUFB ? sa1 : sa0;
    uint32_t sb = BUFB ? sb1 : sb0;
    uint32_t o0 = (uint32_t)tid * 16u;
    uint32_t o1 = (uint32_t)(ROWS_PB + tid) * 16u;
    cp_async16(sa + o0, g0a + CH * NF);
    cp_async16(sa + o1, g1a + CH * NF);
    cp_async16(sb + o0, g0b + CH * NF);
    cp_async16(sb + o1, g1b + CH * NF);
    cp_commit();
}

// compute chunk CH (8 columns) from buffer (CH&1)
template <int CH, int J>
__device__ __forceinline__ void compute_rec(const float4* sA, const float4* sB,
                                            int tid, float (&se)[NSLICE],
                                            float& dlab, float& msea) {
    if constexpr (J < NF) {
        float4 a = sA[tid * NF + J];
        float4 b = sB[tid * NF + J];
        constexpr int C = (CH * NF + J) * 4;
        handle_col<C + 0>(a.x, b.x, se, dlab, msea);
        handle_col<C + 1>(a.y, b.y, se, dlab, msea);
        handle_col<C + 2>(a.z, b.z, se, dlab, msea);
        handle_col<C + 3>(a.w, b.w, se, dlab, msea);
        compute_rec<CH, J + 1>(sA, sB, tid, se, dlab, msea);
    }
}

template <int CH>
__device__ __forceinline__ void pipe_loop(
        float4 (*bufA)[ROWS_PB * NF], float4 (*bufB)[ROWS_PB * NF],
        uint32_t sa0, uint32_t sa1, uint32_t sb0, uint32_t sb1, int tid,
        const float4* g0a, const float4* g1a,
        const float4* g0b, const float4* g1b,
        float (&se)[NSLICE], float& dlab, float& msea) {
    if constexpr (CH < NCH) {
        if constexpr (CH + 1 < NCH)
            issue_chunk<CH + 1>(sa0, sa1, sb0, sb1, tid, g0a, g1a, g0b, g1b);
        cp_wait<(CH + 1 < NCH) ? 1 : 0>();
        __syncthreads();                       // all threads' chunk-CH data visible
        compute_rec<CH, 0>(bufA[CH & 1], bufB[CH & 1], tid, se, dlab, msea);
        __syncthreads();                       // buffer free before CH+2 issues into it
        pipe_loop<CH + 1>(bufA, bufB, sa0, sa1, sb0, sb1, tid,
                          g0a, g1a, g0b, g1b, se, dlab, msea);
    }
}

// ---------------- main pass: MSE + CE + minmax + male count ----------------
__global__ void __launch_bounds__(ROWS_PB, 4) main_kernel(
    const float* __restrict__ enc, const float* __restrict__ dec,
    const float* __restrict__ tru, const float* __restrict__ lab, int B) {

    __shared__ float4   s_a[2][ROWS_PB * NF];   // 16 KB
    __shared__ float4   s_b[2][ROWS_PB * NF];   // 16 KB
    __shared__ float    s_ce[8], s_mse[8];
    __shared__ unsigned s_mn[10], s_mx[10];
    __shared__ int      s_male;

    int tid  = threadIdx.x;
    int wid  = tid >> 5;
    int lane = tid & 31;
    if (tid < 10) { s_mn[tid] = 0xFFFFFFFFu; s_mx[tid] = 0u; }
    if (tid == 0) s_male = 0;

    int base   = blockIdx.x * ROWS_PB;
    int maxrow = min(ROWS_PB, B - base) - 1;
    int row    = base + tid;
    bool valid = (row < B);

    const float4* dp = (const float4*)(dec + (size_t)base * NCOLS);
    const float4* tp = (const float4*)(tru + (size_t)base * NCOLS);

    // per-thread gather bases: p0 = tid, p1 = 256+tid; (row,col) = (p/NF, p%NF)
    int r0 = min(tid >> 1, maxrow),            c0 = tid & 1;
    int r1 = min((ROWS_PB + tid) >> 1, maxrow), c1 = (ROWS_PB + tid) & 1;
    const float4* g0a = dp + r0 * NF4 + c0;
    const float4* g1a = dp + r1 * NF4 + c1;
    const float4* g0b = tp + r0 * NF4 + c0;
    const float4* g1b = tp + r1 * NF4 + c1;

    uint32_t sa0 = (uint32_t)__cvta_generic_to_shared(&s_a[0][0]);
    uint32_t sa1 = (uint32_t)__cvta_generic_to_shared(&s_a[1][0]);
    uint32_t sb0 = (uint32_t)__cvta_generic_to_shared(&s_b[0][0]);
    uint32_t sb1 = (uint32_t)__cvta_generic_to_shared(&s_b[1][0]);

    float se[NSLICE];
#pragma unroll
    for (int i = 0; i < NSLICE; i++) se[i] = 0.0f;
    float dlab = 0.0f, msea = 0.0f;

    issue_chunk<0>(sa0, sa1, sb0, sb1, tid, g0a, g1a, g0b, g1b);
    pipe_loop<0>(s_a, s_b, sa0, sa1, sb0, sb1, tid,
                 g0a, g1a, g0b, g1b, se, dlab, msea);

    float ce_row = 0.0f;
#pragma unroll
    for (int i = 0; i < NSLICE; i++) ce_row += __logf(se[i]);
    ce_row -= dlab;
    if (!valid) { ce_row = 0.0f; msea = 0.0f; }

    // enc min/max + male flag (thread-per-row)
    float emn[10], emx[10];
    bool is_male = false;
    if (valid) {
        const float* ep = enc + (size_t)row * 11;
#pragma unroll
        for (int j = 0; j < 10; j++) {
            float v = __ldg(ep + j);
            emn[j] = v; emx[j] = v;
        }
        is_male = (__ldg(lab + row) < 0.5f);
    } else {
#pragma unroll
        for (int j = 0; j < 10; j++) {
            emn[j] = __int_as_float(0x7F800000);   // +inf
            emx[j] = __int_as_float(0xFF800000);   // -inf
        }
    }

    // warp reductions
    float cer = ce_row, mser = msea;
#pragma unroll
    for (int o = 16; o; o >>= 1) {
        cer  += __shfl_xor_sync(0xFFFFFFFFu, cer,  o);
        mser += __shfl_xor_sync(0xFFFFFFFFu, mser, o);
    }
#pragma unroll
    for (int j = 0; j < 10; j++) {
        float mn = emn[j], mx = emx[j];
#pragma unroll
        for (int o = 16; o; o >>= 1) {
            mn = fminf(mn, __shfl_xor_sync(0xFFFFFFFFu, mn, o));
            mx = fmaxf(mx, __shfl_xor_sync(0xFFFFFFFFu, mx, o));
        }
        emn[j] = mn; emx[j] = mx;
    }
    unsigned mb = __ballot_sync(0xFFFFFFFFu, is_male);

    if (lane == 0) {
        s_ce[wid]  = cer;
        s_mse[wid] = mser;
#pragma unroll
        for (int j = 0; j < 10; j++) {
            atomicMin(&s_mn[j], f2o(emn[j]));
            atomicMax(&s_mx[j], f2o(emx[j]));
        }
        atomicAdd(&s_male, __popc(mb));
    }
    __syncthreads();

    if (tid == 0) {
        float c = 0.0f, m = 0.0f;
#pragma unroll
        for (int w = 0; w < 8; w++) { c += s_ce[w]; m += s_mse[w]; }
        atomicAdd(&g_ce,  (double)c);
        atomicAdd(&g_mse, (double)m);
        atomicAdd(&g_male, s_male);
    }
    if (tid < 10) {
        atomicMin(&g_min[tid], s_mn[tid]);
        atomicMax(&g_max[tid], s_mx[tid]);
    }
}

// ---------------- histogram pass (one sex per blockIdx.y) ------------------
__global__ void __launch_bounds__(256) hist_kernel(
    const float* __restrict__ enc, const float* __restrict__ lab, int B) {

    __shared__ int sh[10 * NBINS];   // 32 KB
    for (int i = threadIdx.x; i < 10 * NBINS; i += 256) sh[i] = 0;
    __syncthreads();

    int sex = blockIdx.y;   // 0 = male (label 0), 1 = female (label 1)

    float mnv[10], rng[10];
#pragma unroll
    for (int j = 0; j < 10; j++) {
        mnv[j] = o2f(g_min[j]);
        rng[j] = o2f(g_max[j]) - mnv[j];
    }

    int stride = gridDim.x * blockDim.x;
    for (int row = blockIdx.x * blockDim.x + threadIdx.x; row < B; row += stride) {
        float lv = __ldg(lab + row);
        int rsex = (lv < 0.5f) ? 0 : 1;
        if (rsex != sex) continue;
        const float* ep = enc + (size_t)row * 11;
#pragma unroll
        for (int j = 0; j < 10; j++) {
            float x = __ldg(ep + j);
            // match jax fp32: t = (x-mn)/(mx-mn); idx = clip(floor(t*800),0,799)
            float t  = __fdiv_rn(x - mnv[j], rng[j]);
            float ft = floorf(__fmul_rn(t, (float)NBINS));
            int idx = (int)ft;
            idx = max(0, min(NBINS - 1, idx));
            atomicAdd(&sh[j * NBINS + idx], 1);
        }
    }
    __syncthreads();

    int* gh = &g_hist[sex][0][0];
    for (int i = threadIdx.x; i < 10 * NBINS; i += 256) {
        int v = sh[i];
        if (v) atomicAdd(&gh[i], v);
    }
}

// ---------------- finalize: multi-block JSD + combine + scratch reset ------
__global__ void __launch_bounds__(256) finalize_kernel(float* __restrict__ out, int B) {
    __shared__ double sred[8];

    int nmale = g_male;                 // read before any reset
    float nm_inv = 1.0f / (float)nmale;
    float nf_inv = 1.0f / (float)(B - nmale);
    const float eps = 1e-12f;

    float acc = 0.0f;
    int* hm = &g_hist[0][0][0];
    int* hf = &g_hist[1][0][0];
    for (int i = blockIdx.x * 256 + threadIdx.x; i < 10 * NBINS;
         i += FIN_BLOCKS * 256) {
        int a = hm[i], b = hf[i];
        hm[i] = 0; hf[i] = 0;           // re-zero for next replay
        float m = (float)a * nm_inv;
        float f = (float)b * nf_inv;
        float mid = 0.5f * (m + f);
        float inv_mid = 1.0f / (mid + eps);
        if (m > 0.0f) acc += m * logf((m + eps) * inv_mid);
        if (f > 0.0f) acc += f * logf((f + eps) * inv_mid);
    }

    double d = (double)acc;
#pragma unroll
    for (int o = 16; o; o >>= 1)
        d += __shfl_xor_sync(0xFFFFFFFFu, d, o);
    int wid = threadIdx.x >> 5;
    if ((threadIdx.x & 31) == 0) sred[wid] = d;
    __syncthreads();

    if (threadIdx.x == 0) {
        double s = 0.0;
#pragma unroll
        for (int w = 0; w < 8; w++) s += sred[w];
        atomicAdd(&g_kld, s);
        __threadfence();
        unsigned ticket = atomicAdd(&g_done, 1u);
        if (ticket == FIN_BLOCKS - 1) {
            double kld = 0.5 * atomicAdd(&g_kld, 0.0);
            double mse = g_mse / (double)B;
            double ce  = g_ce  / (double)B;
            out[0] = (float)((1.0 - RATIO_JSD) * (mse + ce) + RATIO_JSD * kld);
            out[1] = (float)mse;
            out[2] = (float)ce;
            out[3] = (float)(RATIO_JSD * kld);
            // reset scalar scratch for the next replay
            g_mse = 0.0; g_ce = 0.0; g_kld = 0.0;
            g_male = 0; g_done = 0u;
#pragma unroll
            for (int j = 0; j < 10; j++) {
                g_min[j] = 0xFFFFFFFFu;
                g_max[j] = 0u;
            }
        }
    }
}

// ---------------- launch ----------------------------------------------------
extern "C" void kernel_launch(void* const* d_in, const int* in_sizes, int n_in,
                              void* d_out, int out_size) {
    const float* enc = (const float*)d_in[0];   // [B,11]
    const float* dec = (const float*)d_in[1];   // [B,168]
    const float* tru = (const float*)d_in[2];   // [B,168]
    const float* lab = (const float*)d_in[3];   // [B,1]
    int B = in_sizes[3];

    int blocks = (B + ROWS_PB - 1) / ROWS_PB;
    main_kernel<<<blocks, ROWS_PB>>>(enc, dec, tru, lab, B);

    dim3 hgrid(256, 2, 1);
    hist_kernel<<<hgrid, 256>>>(enc, lab, B);

    finalize_kernel<<<FIN_BLOCKS, 256>>>((float*)d_out, B);
}

// round 9
// speedup vs baseline: 1.3707x; 1.0686x over previous
#include <cuda_runtime.h>
#include <cstdint>

// ---------------------------------------------------------------------------
// MultiLoss_JSD: fused MSE + 17-head CE + histogram JSD
// B = 262144 rows; decoded/true: [B,168] f32; encoded: [B,11] f32; label: [B,1] f32
// out: 4 floats [multi, mse, ce, 0.1*kld]
// ---------------------------------------------------------------------------

#define NSLICE 17
#define NBINS  800
#define NCOLS  168
#define NF4    42          // float4s per row
#define NF     2           // float4s per chunk per row
#define NCH    21          // 21 chunks * 8 cols = 168
#define STAGES 4
#define ROWS_PB 128
#define RATIO_JSD 0.1
#define FIN_BLOCKS 16

__host__ __device__ constexpr int slice_of(int c) {
    const int S[NSLICE][2] = {
        {1,10},{12,29},{30,33},{33,40},{40,64},{64,79},{79,84},{84,94},{94,96},
        {96,99},{99,105},{105,113},{116,122},{122,128},{128,151},{151,159},{160,165}};
    for (int i = 0; i < NSLICE; i++)
        if (c >= S[i][0] && c < S[i][1]) return i;
    return -1;  // MSE column
}

// ---------------- scratch (device globals; zero at module load) ------------
// finalize_kernel re-zeros everything it consumed, so no init kernel needed.
__device__ double   g_mse;
__device__ double   g_ce;
__device__ double   g_kld;
__device__ unsigned g_done;
__device__ unsigned g_min[10];
__device__ unsigned g_max[10];
__device__ int      g_male;
__device__ int      g_hist[2][10][NBINS];   // [sex][dim][bin]

__device__ __forceinline__ unsigned f2o(float f) {
    unsigned u = __float_as_uint(f);
    return (u & 0x80000000u) ? ~u : (u | 0x80000000u);
}
__device__ __forceinline__ float o2f(unsigned u) {
    return (u & 0x80000000u) ? __uint_as_float(u & 0x7FFFFFFFu)
                             : __uint_as_float(~u);
}

// ---------------- cp.async helpers -----------------------------------------
__device__ __forceinline__ void cp_async16(uint32_t s, const void* g) {
    asm volatile("cp.async.cg.shared.global [%0], [%1], 16;" :: "r"(s), "l"(g));
}
__device__ __forceinline__ void cp_commit() {
    asm volatile("cp.async.commit_group;" ::: "memory");
}
template <int N>
__device__ __forceinline__ void cp_wait() {
    asm volatile("cp.async.wait_group %0;" :: "n"(N) : "memory");
}

// ---------------- compile-time column handling -----------------------------
template <int C>
__device__ __forceinline__ void handle_col(float d, float t,
                                           float (&se)[NSLICE],
                                           float& dlab, float& msea) {
    constexpr int s = slice_of(C);
    if constexpr (s >= 0) {
        se[s] += __expf(d);
        dlab = __fmaf_rn(d, t, dlab);   // t is exact one-hot 0/1
    } else {
        float diff = d - t;
        msea = __fmaf_rn(diff, diff, msea);
    }
}

// issue chunk CH into ring stage CH%4: 4 cp.async per thread, lane-contiguous
template <int CH>
__device__ __forceinline__ void issue_chunk(uint32_t sa_base, uint32_t sb_base,
                                            int tid,
                                            const float4* g0a, const float4* g1a,
                                            const float4* g0b, const float4* g1b) {
    constexpr uint32_t STG = (uint32_t)(CH & (STAGES - 1));
    constexpr uint32_t SOFF = STG * ROWS_PB * NF * 16u;
    uint32_t o0 = SOFF + (uint32_t)tid * 16u;
    uint32_t o1 = SOFF + (uint32_t)(ROWS_PB + tid) * 16u;
    cp_async16(sa_base + o0, g0a + CH * NF);
    cp_async16(sa_base + o1, g1a + CH * NF);
    cp_async16(sb_base + o0, g0b + CH * NF);
    cp_async16(sb_base + o1, g1b + CH * NF);
    cp_commit();
}

// compute chunk CH (8 columns) from ring stage CH%4
template <int CH, int J>
__device__ __forceinline__ void compute_rec(const float4* sA, const float4* sB,
                                            int tid, float (&se)[NSLICE],
                                            float& dlab, float& msea) {
    if constexpr (J < NF) {
        float4 a = sA[tid * NF + J];
        float4 b = sB[tid * NF + J];
        constexpr int C = (CH * NF + J) * 4;
        handle_col<C + 0>(a.x, b.x, se, dlab, msea);
        handle_col<C + 1>(a.y, b.y, se, dlab, msea);
        handle_col<C + 2>(a.z, b.z, se, dlab, msea);
        handle_col<C + 3>(a.w, b.w, se, dlab, msea);
        compute_rec<CH, J + 1>(sA, sB, tid, se, dlab, msea);
    }
}

template <int CH>
__device__ __forceinline__ void pipe_loop(
        float4 (*bufA)[ROWS_PB * NF], float4 (*bufB)[ROWS_PB * NF],
        uint32_t sa_base, uint32_t sb_base, int tid,
        const float4* g0a, const float4* g1a,
        const float4* g0b, const float4* g1b,
        float (&se)[NSLICE], float& dlab, float& msea) {
    if constexpr (CH < NCH) {
        // groups outstanding after chunk CH's data must be ready:
        // issued through CH+2 so far, so allow 2 groups still in flight.
        constexpr int OUT = (CH + 2 < NCH) ? 2 : (NCH - 1 - CH);
        cp_wait<OUT>();
        __syncthreads();   // (a) chunk CH visible to all; (b) compute CH-1 done
        if constexpr (CH + 3 < NCH)
            issue_chunk<CH + 3>(sa_base, sb_base, tid, g0a, g1a, g0b, g1b);
        compute_rec<CH, 0>(bufA[CH & (STAGES - 1)], bufB[CH & (STAGES - 1)],
                           tid, se, dlab, msea);
        pipe_loop<CH + 1>(bufA, bufB, sa_base, sb_base, tid,
                          g0a, g1a, g0b, g1b, se, dlab, msea);
    }
}

// ---------------- main pass: MSE + CE + minmax + male count ----------------
__global__ void __launch_bounds__(ROWS_PB, 8) main_kernel(
    const float* __restrict__ enc, const float* __restrict__ dec,
    const float* __restrict__ tru, const float* __restrict__ lab, int B) {

    __shared__ float4   s_a[STAGES][ROWS_PB * NF];   // 16 KB
    __shared__ float4   s_b[STAGES][ROWS_PB * NF];   // 16 KB
    __shared__ float    s_ce[4], s_mse[4];
    __shared__ unsigned s_mn[10], s_mx[10];
    __shared__ int      s_male;

    int tid  = threadIdx.x;
    int wid  = tid >> 5;
    int lane = tid & 31;
    if (tid < 10) { s_mn[tid] = 0xFFFFFFFFu; s_mx[tid] = 0u; }
    if (tid == 0) s_male = 0;

    int base   = blockIdx.x * ROWS_PB;
    int maxrow = min(ROWS_PB, B - base) - 1;
    int row    = base + tid;
    bool valid = (row < B);

    const float4* dp = (const float4*)(dec + (size_t)base * NCOLS);
    const float4* tp = (const float4*)(tru + (size_t)base * NCOLS);

    // per-thread gather: p0 = tid, p1 = 128+tid; (row,col) = (p/NF, p%NF)
    int r0 = min(tid >> 1, maxrow);
    int r1 = min((ROWS_PB + tid) >> 1, maxrow);
    int c  = tid & 1;
    const float4* g0a = dp + r0 * NF4 + c;
    const float4* g1a = dp + r1 * NF4 + c;
    const float4* g0b = tp + r0 * NF4 + c;
    const float4* g1b = tp + r1 * NF4 + c;

    uint32_t sa_base = (uint32_t)__cvta_generic_to_shared(&s_a[0][0]);
    uint32_t sb_base = (uint32_t)__cvta_generic_to_shared(&s_b[0][0]);

    float se[NSLICE];
#pragma unroll
    for (int i = 0; i < NSLICE; i++) se[i] = 0.0f;
    float dlab = 0.0f, msea = 0.0f;

    // prologue: fill 3 of 4 ring stages
    issue_chunk<0>(sa_base, sb_base, tid, g0a, g1a, g0b, g1b);
    issue_chunk<1>(sa_base, sb_base, tid, g0a, g1a, g0b, g1b);
    issue_chunk<2>(sa_base, sb_base, tid, g0a, g1a, g0b, g1b);
    pipe_loop<0>(s_a, s_b, sa_base, sb_base, tid,
                 g0a, g1a, g0b, g1b, se, dlab, msea);

    float ce_row = 0.0f;
#pragma unroll
    for (int i = 0; i < NSLICE; i++) ce_row += __logf(se[i]);
    ce_row -= dlab;
    if (!valid) { ce_row = 0.0f; msea = 0.0f; }

    // enc min/max + male flag (thread-per-row)
    float emn[10], emx[10];
    bool is_male = false;
    if (valid) {
        const float* ep = enc + (size_t)row * 11;
#pragma unroll
        for (int j = 0; j < 10; j++) {
            float v = __ldg(ep + j);
            emn[j] = v; emx[j] = v;
        }
        is_male = (__ldg(lab + row) < 0.5f);
    } else {
#pragma unroll
        for (int j = 0; j < 10; j++) {
            emn[j] = __int_as_float(0x7F800000);   // +inf
            emx[j] = __int_as_float(0xFF800000);   // -inf
        }
    }

    // warp reductions
    float cer = ce_row, mser = msea;
#pragma unroll
    for (int o = 16; o; o >>= 1) {
        cer  += __shfl_xor_sync(0xFFFFFFFFu, cer,  o);
        mser += __shfl_xor_sync(0xFFFFFFFFu, mser, o);
    }
#pragma unroll
    for (int j = 0; j < 10; j++) {
        float mn = emn[j], mx = emx[j];
#pragma unroll
        for (int o = 16; o; o >>= 1) {
            mn = fminf(mn, __shfl_xor_sync(0xFFFFFFFFu, mn, o));
            mx = fmaxf(mx, __shfl_xor_sync(0xFFFFFFFFu, mx, o));
        }
        emn[j] = mn; emx[j] = mx;
    }
    unsigned mb = __ballot_sync(0xFFFFFFFFu, is_male);

    if (lane == 0) {
        s_ce[wid]  = cer;
        s_mse[wid] = mser;
#pragma unroll
        for (int j = 0; j < 10; j++) {
            atomicMin(&s_mn[j], f2o(emn[j]));
            atomicMax(&s_mx[j], f2o(emx[j]));
        }
        atomicAdd(&s_male, __popc(mb));
    }
    __syncthreads();

    if (tid == 0) {
        float c2 = 0.0f, m2 = 0.0f;
#pragma unroll
        for (int w = 0; w < 4; w++) { c2 += s_ce[w]; m2 += s_mse[w]; }
        atomicAdd(&g_ce,  (double)c2);
        atomicAdd(&g_mse, (double)m2);
        atomicAdd(&g_male, s_male);
    }
    if (tid < 10) {
        atomicMin(&g_min[tid], s_mn[tid]);
        atomicMax(&g_max[tid], s_mx[tid]);
    }
}

// ---------------- histogram pass (one sex per blockIdx.y) ------------------
__global__ void __launch_bounds__(256) hist_kernel(
    const float* __restrict__ enc, const float* __restrict__ lab, int B) {

    __shared__ int sh[10 * NBINS];   // 32 KB
    for (int i = threadIdx.x; i < 10 * NBINS; i += 256) sh[i] = 0;
    __syncthreads();

    int sex = blockIdx.y;   // 0 = male (label 0), 1 = female (label 1)

    float mnv[10], rng[10];
#pragma unroll
    for (int j = 0; j < 10; j++) {
        mnv[j] = o2f(g_min[j]);
        rng[j] = o2f(g_max[j]) - mnv[j];
    }

    int stride = gridDim.x * blockDim.x;
    for (int row = blockIdx.x * blockDim.x + threadIdx.x; row < B; row += stride) {
        float lv = __ldg(lab + row);
        int rsex = (lv < 0.5f) ? 0 : 1;
        if (rsex != sex) continue;
        const float* ep = enc + (size_t)row * 11;
#pragma unroll
        for (int j = 0; j < 10; j++) {
            float x = __ldg(ep + j);
            // match jax fp32: t = (x-mn)/(mx-mn); idx = clip(floor(t*800),0,799)
            float t  = __fdiv_rn(x - mnv[j], rng[j]);
            float ft = floorf(__fmul_rn(t, (float)NBINS));
            int idx = (int)ft;
            idx = max(0, min(NBINS - 1, idx));
            atomicAdd(&sh[j * NBINS + idx], 1);
        }
    }
    __syncthreads();

    int* gh = &g_hist[sex][0][0];
    for (int i = threadIdx.x; i < 10 * NBINS; i += 256) {
        int v = sh[i];
        if (v) atomicAdd(&gh[i], v);
    }
}

// ---------------- finalize: multi-block JSD + combine + scratch reset ------
__global__ void __launch_bounds__(256) finalize_kernel(float* __restrict__ out, int B) {
    __shared__ double sred[8];

    int nmale = g_male;                 // read before any reset
    float nm_inv = 1.0f / (float)nmale;
    float nf_inv = 1.0f / (float)(B - nmale);
    const float eps = 1e-12f;

    float acc = 0.0f;
    int* hm = &g_hist[0][0][0];
    int* hf = &g_hist[1][0][0];
    for (int i = blockIdx.x * 256 + threadIdx.x; i < 10 * NBINS;
         i += FIN_BLOCKS * 256) {
        int a = hm[i], b = hf[i];
        hm[i] = 0; hf[i] = 0;           // re-zero for next replay
        float m = (float)a * nm_inv;
        float f = (float)b * nf_inv;
        float mid = 0.5f * (m + f);
        float inv_mid = 1.0f / (mid + eps);
        if (m > 0.0f) acc += m * logf((m + eps) * inv_mid);
        if (f > 0.0f) acc += f * logf((f + eps) * inv_mid);
    }

    double d = (double)acc;
#pragma unroll
    for (int o = 16; o; o >>= 1)
        d += __shfl_xor_sync(0xFFFFFFFFu, d, o);
    int wid = threadIdx.x >> 5;
    if ((threadIdx.x & 31) == 0) sred[wid] = d;
    __syncthreads();

    if (threadIdx.x == 0) {
        double s = 0.0;
#pragma unroll
        for (int w = 0; w < 8; w++) s += sred[w];
        atomicAdd(&g_kld, s);
        __threadfence();
        unsigned ticket = atomicAdd(&g_done, 1u);
        if (ticket == FIN_BLOCKS - 1) {
            double kld = 0.5 * atomicAdd(&g_kld, 0.0);
            double mse = g_mse / (double)B;
            double ce  = g_ce  / (double)B;
            out[0] = (float)((1.0 - RATIO_JSD) * (mse + ce) + RATIO_JSD * kld);
            out[1] = (float)mse;
            out[2] = (float)ce;
            out[3] = (float)(RATIO_JSD * kld);
            // reset scalar scratch for the next replay
            g_mse = 0.0; g_ce = 0.0; g_kld = 0.0;
            g_male = 0; g_done = 0u;
#pragma unroll
            for (int j = 0; j < 10; j++) {
                g_min[j] = 0xFFFFFFFFu;
                g_max[j] = 0u;
            }
        }
    }
}

// ---------------- launch ----------------------------------------------------
extern "C" void kernel_launch(void* const* d_in, const int* in_sizes, int n_in,
                              void* d_out, int out_size) {
    const float* enc = (const float*)d_in[0];   // [B,11]
    const float* dec = (const float*)d_in[1];   // [B,168]
    const float* tru = (const float*)d_in[2];   // [B,168]
    const float* lab = (const float*)d_in[3];   // [B,1]
    int B = in_sizes[3];

    int blocks = (B + ROWS_PB - 1) / ROWS_PB;
    main_kernel<<<blocks, ROWS_PB>>>(enc, dec, tru, lab, B);

    dim3 hgrid(256, 2, 1);
    hist_kernel<<<hgrid, 256>>>(enc, lab, B);

    finalize_kernel<<<FIN_BLOCKS, 256>>>((float*)d_out, B);
}